// round 15
// baseline (speedup 1.0000x reference)
#include <cuda_runtime.h>
#include <cuda_fp16.h>
#include <cstdint>

#define BATCH 512
#define GS 2048
#define PARAM 64
#define OGS 1024
#define KDIM 128
#define NDIM 64
#define TILE_ROWS 64
#define GX 16                          // grid.x = OGS / TILE_ROWS

#define PF  136                        // f32 pitch of A tile (544B: conflict-free LDS.64)
#define PFB (PF * 4)
#define SMEM_BYTES (TILE_ROWS * PFB)   // 34816

__device__ unsigned int g_order[BATCH * GS];
// B mma-fragments (single fp16): [ng(2)][kc(8)][g(2)][lane(32)] uint4. 16KB.
__device__ __align__(16) uint4 g_Bfrag[2 * 8 * 2 * 32];
__device__ int g_flag[BATCH];
__device__ int g_bflag;
__device__ unsigned int g_done;

__device__ __forceinline__ uint32_t smem_u32(const void* p) {
    uint32_t a;
    asm("{ .reg .u64 t; cvta.to.shared.u64 t, %1; cvt.u32.u64 %0, t; }" : "=r"(a) : "l"(p));
    return a;
}
__device__ __forceinline__ int ld_acquire(const int* p) {
    int v;
    asm volatile("ld.acquire.gpu.global.b32 %0, [%1];" : "=r"(v) : "l"(p) : "memory");
    return v;
}
__device__ __forceinline__ void st_release(int* p, int v) {
    asm volatile("st.release.gpu.global.b32 [%0], %1;" :: "l"(p), "r"(v) : "memory");
}

#define CPASYNC16(dst, src) \
    asm volatile("cp.async.cg.shared.global [%0], [%1], 16;" \
        :: "r"(dst), "l"(src) : "memory")

#define MMA(d, a, b0v, b1v) \
    asm volatile("mma.sync.aligned.m16n8k16.row.col.f32.f16.f16.f32 " \
        "{%0,%1,%2,%3},{%4,%5,%6,%7},{%8,%9},{%0,%1,%2,%3};" \
        : "+f"((d)[0]), "+f"((d)[1]), "+f"((d)[2]), "+f"((d)[3]) \
        : "r"((a)[0]), "r"((a)[1]), "r"((a)[2]), "r"((a)[3]), "r"(b0v), "r"(b1v))

// fp16 split: hi = f16x2(vx lo-half, vy hi-half); lo = f16x2 of residuals.
__device__ __forceinline__ void split_pair(float vx, float vy,
                                           uint32_t& hi, uint32_t& lo) {
    asm("cvt.rn.f16x2.f32 %0, %1, %2;" : "=r"(hi) : "f"(vy), "f"(vx));
    float hx, hy;
    asm("{ .reg .b16 l, h; mov.b32 {l, h}, %2; cvt.f32.f16 %0, l; cvt.f32.f16 %1, h; }"
        : "=f"(hx), "=f"(hy) : "r"(hi));
    float rx = vx - hx;
    float ry = vy - hy;
    asm("cvt.rn.f16x2.f32 %0, %1, %2;" : "=r"(lo) : "f"(ry), "f"(rx));
}

__device__ __forceinline__ void ce(unsigned long long& a, unsigned long long& b, bool up) {
    if ((a > b) == up) { unsigned long long t = a; a = b; b = t; }
}
__device__ __forceinline__ void merge8(unsigned long long* k, bool up) {
    ce(k[0], k[4], up); ce(k[1], k[5], up); ce(k[2], k[6], up); ce(k[3], k[7], up);
    ce(k[0], k[2], up); ce(k[1], k[3], up); ce(k[4], k[6], up); ce(k[5], k[7], up);
    ce(k[0], k[1], up); ce(k[2], k[3], up); ce(k[4], k[5], up); ce(k[6], k[7], up);
}

// ---------------------------------------------------------------------------
// Fused kernel. grid = (16, 512), block = 256, 3 CTAs/SM (smem 34.8KB).
// Warp w: rows (w&3)*16 (M16), cols (w>>2)*32 (N32). fp16 2-term.
// ---------------------------------------------------------------------------
__global__ __launch_bounds__(256, 3) void fused_kernel(const float* __restrict__ x,
                                                       const float* __restrict__ trafo,
                                                       float* __restrict__ out) {
    extern __shared__ char smem[];
    __shared__ unsigned s_last;

    const int y = blockIdx.y;
    const int bid = blockIdx.x + y * GX;
    const int tileRow = blockIdx.x * TILE_ROWS;
    const int t = threadIdx.x;
    const int wid = t >> 5;
    const int lid = t & 31;
    const uint32_t sb32 = smem_u32(smem);

    // ---- B-fragment table (bid 0; 512 slots of 1 uint4, 2 per thread) ----
    if (bid == 0) {
        #pragma unroll
        for (int half = 0; half < 2; half++) {
            int it = t + 256 * half;
            int ng = it >> 8;
            int kc = (it >> 5) & 7;
            int lane = it & 31;
            int n_base = ng * 32 + (lane >> 2);
            int k_base = kc * 16 + 2 * (lane & 3);
            uint32_t rh[8];
            #pragma unroll
            for (int nt = 0; nt < 4; nt++)
                #pragma unroll
                for (int r = 0; r < 2; r++) {
                    int n = n_base + 8 * nt;
                    int k = k_base + 8 * r;
                    __half2 h2 = __floats2half2_rn(trafo[k * NDIM + n],
                                                   trafo[(k + 1) * NDIM + n]);
                    rh[2 * nt + r] = *(uint32_t*)&h2;
                }
            uint4* dst = g_Bfrag + (ng * 8 + kc) * 64 + lane;
            dst[0]  = make_uint4(rh[0], rh[1], rh[2], rh[3]);   // nt0, nt1
            dst[32] = make_uint4(rh[4], rh[5], rh[6], rh[7]);   // nt2, nt3
        }
        __syncthreads();
        __threadfence();
        if (t == 0) st_release(&g_bflag, 1);
    }

    // ---- Sort batch `bid` (bid < 512): 256 threads x 8 keys ----
    if (bid < BATCH) {
        unsigned long long* keys = (unsigned long long*)smem;   // 16KB overlay
        const float* xb = x + (size_t)bid * GS * PARAM;

        unsigned long long key[8];
        #pragma unroll
        for (int i = 0; i < 8; i++) {
            int e = 8 * t + i;
            unsigned u = __float_as_uint(xb[(size_t)e * PARAM + (PARAM - 1)]);
            unsigned m = (u & 0x80000000u) ? ~u : (u | 0x80000000u);
            key[i] = ((unsigned long long)(~m) << 32) | (unsigned)e;
        }

        ce(key[0], key[1], true);  ce(key[2], key[3], false);
        ce(key[4], key[5], true);  ce(key[6], key[7], false);
        ce(key[0], key[2], true);  ce(key[1], key[3], true);
        ce(key[0], key[1], true);  ce(key[2], key[3], true);
        ce(key[4], key[6], false); ce(key[5], key[7], false);
        ce(key[4], key[5], false); ce(key[6], key[7], false);
        merge8(key, (t & 1) == 0);

        #pragma unroll
        for (int k = 16; k <= 256; k <<= 1) {
            bool up = ((t & (k >> 3)) == 0);
            #pragma unroll
            for (int j = k >> 1; j >= 8; j >>= 1) {
                int d = j >> 3;
                bool keepmin = (((t & d) == 0) == up);
                #pragma unroll
                for (int i = 0; i < 8; i++) {
                    unsigned long long p = __shfl_xor_sync(0xffffffffu, key[i], d);
                    key[i] = keepmin ? (key[i] < p ? key[i] : p) : (key[i] > p ? key[i] : p);
                }
            }
            merge8(key, up);
        }

        for (int k = 512; k <= GS; k <<= 1) {
            #pragma unroll
            for (int i = 0; i < 8; i++) keys[8 * t + i] = key[i];
            __syncthreads();
            for (int j = k >> 1; j >= 256; j >>= 1) {
                #pragma unroll
                for (int q0 = 0; q0 < 4; q0++) {
                    int q = t + 256 * q0;
                    int i = ((q & ~(j - 1)) << 1) | (q & (j - 1));
                    bool up2 = ((i & k) == 0);
                    unsigned long long a = keys[i];
                    unsigned long long c = keys[i | j];
                    if ((a > c) == up2) { keys[i] = c; keys[i | j] = a; }
                }
                __syncthreads();
            }
            #pragma unroll
            for (int i = 0; i < 8; i++) key[i] = keys[8 * t + i];
            bool up = ((t & (k >> 3)) == 0);
            #pragma unroll
            for (int j = 128; j >= 8; j >>= 1) {
                int d = j >> 3;
                bool keepmin = (((t & d) == 0) == up);
                #pragma unroll
                for (int i = 0; i < 8; i++) {
                    unsigned long long p = __shfl_xor_sync(0xffffffffu, key[i], d);
                    key[i] = keepmin ? (key[i] < p ? key[i] : p) : (key[i] > p ? key[i] : p);
                }
            }
            merge8(key, up);
        }

        #pragma unroll
        for (int i = 0; i < 8; i++)
            g_order[bid * GS + 8 * t + i] = (unsigned)(key[i] & 0xffffffffu);

        __syncthreads();   // key reads done; smem reusable by gather
        __threadfence();
        if (t == 0) st_release(&g_flag[bid], 1);
    }

    // ---- Per-warp wait for this batch's order (sorter bid = y <= our bid) ----
    while (ld_acquire(&g_flag[y]) == 0) __nanosleep(64);

    // ---- Per-warp-pair gather via cp.async: pair {p,p+4} fills A rows
    //      16p..16p+15 (source rows 32p..32p+31); each warp 16 src rows. ----
    const int pair = wid & 3;
    {
        const int sub = wid >> 2;
        const int sbase = 32 * pair + 16 * sub;
        const float* xb = x + (size_t)y * GS * PARAM;
        const int lane16 = lid & 15;
        const int rsel = lid >> 4;
        const unsigned* ord = g_order + y * GS + 2 * tileRow + sbase;
        unsigned idx[8];
        #pragma unroll
        for (int pass = 0; pass < 8; pass++)
            idx[pass] = ord[2 * pass + rsel];
        #pragma unroll
        for (int pass = 0; pass < 8; pass++) {
            int s = sbase + 2 * pass + rsel;
            const float* src = xb + (size_t)idx[pass] * PARAM + lane16 * 4;
            uint32_t dst = sb32 + (uint32_t)(s >> 1) * PFB +
                           (uint32_t)(((s & 1) * PARAM + lane16 * 4) * 4);
            CPASYNC16(dst, src);
        }
        asm volatile("cp.async.commit_group;" ::: "memory");
    }

    // ---- Overlap B-table wait with async-copy drain, then pair barrier ----
    while (ld_acquire(&g_bflag) == 0) __nanosleep(64);
    asm volatile("cp.async.wait_group 0;" ::: "memory");
    asm volatile("bar.sync %0, 64;" :: "r"(pair + 1) : "memory");

    // ---- Mainloop: warp w -> rows (w&3)*16, cols (w>>2)*32. fp16 2-term. ----
    const int ng = wid >> 2;
    const int wm = pair * 16;

    uint32_t a_base = sb32 + (uint32_t)(wm + (lid >> 2)) * PFB +
                      (uint32_t)(2 * (lid & 3) * 4);
    const uint32_t ROW8 = 8 * PFB;

    const uint4* Bf = g_Bfrag + ng * (8 * 64) + lid;

    float d[4][4];
    #pragma unroll
    for (int nt = 0; nt < 4; nt++)
        #pragma unroll
        for (int e = 0; e < 4; e++) d[nt][e] = 0.f;

    #pragma unroll
    for (int kc = 0; kc < 8; kc++) {
        uint4 f0 = __ldg(Bf + kc * 64);           // nt0, nt1
        uint4 f1 = __ldg(Bf + kc * 64 + 32);      // nt2, nt3
        const uint32_t ab = a_base + kc * 64;

        float2 L0, L1, L2, L3;
        asm volatile("ld.shared.v2.f32 {%0,%1}, [%2];" : "=f"(L0.x), "=f"(L0.y) : "r"(ab));
        asm volatile("ld.shared.v2.f32 {%0,%1}, [%2];" : "=f"(L1.x), "=f"(L1.y) : "r"(ab + ROW8));
        asm volatile("ld.shared.v2.f32 {%0,%1}, [%2];" : "=f"(L2.x), "=f"(L2.y) : "r"(ab + 32));
        asm volatile("ld.shared.v2.f32 {%0,%1}, [%2];" : "=f"(L3.x), "=f"(L3.y) : "r"(ab + ROW8 + 32));

        uint32_t ah[4], al[4];
        split_pair(L0.x, L0.y, ah[0], al[0]);
        split_pair(L1.x, L1.y, ah[1], al[1]);
        split_pair(L2.x, L2.y, ah[2], al[2]);
        split_pair(L3.x, L3.y, ah[3], al[3]);

        MMA(d[0], ah, f0.x, f0.y);
        MMA(d[1], ah, f0.z, f0.w);
        MMA(d[2], ah, f1.x, f1.y);
        MMA(d[3], ah, f1.z, f1.w);
        MMA(d[0], al, f0.x, f0.y);
        MMA(d[1], al, f0.z, f0.w);
        MMA(d[2], al, f1.x, f1.y);
        MMA(d[3], al, f1.z, f1.w);
    }

    // ---- Epilogue: direct float2 stores (per-warp) ----
    float* baseo = out + ((size_t)y * OGS + tileRow) * NDIM;
    const int wn = ng * 32;
    #pragma unroll
    for (int nt = 0; nt < 4; nt++) {
        int r = wm + (lid >> 2);
        int c = wn + 8 * nt + 2 * (lid & 3);
        *(float2*)(baseo + (size_t)r * NDIM + c) = make_float2(d[nt][0], d[nt][1]);
        *(float2*)(baseo + (size_t)(r + 8) * NDIM + c) = make_float2(d[nt][2], d[nt][3]);
    }

    // ---- Flag reset by the last CTA to finish ----
    __syncthreads();
    if (t == 0) {
        unsigned done = atomicAdd(&g_done, 1u);
        s_last = (done == (unsigned)(GX * BATCH - 1)) ? 1u : 0u;
    }
    __syncthreads();
    if (s_last) {
        for (int i = t; i < BATCH; i += 256) g_flag[i] = 0;
        if (t == 0) { g_bflag = 0; g_done = 0u; }
    }
}

extern "C" void kernel_launch(void* const* d_in, const int* in_sizes, int n_in,
                              void* d_out, int out_size) {
    const float* x     = (const float*)d_in[0];
    const float* trafo = (const float*)d_in[1];
    float* out         = (float*)d_out;

    cudaFuncSetAttribute(fused_kernel, cudaFuncAttributeMaxDynamicSharedMemorySize,
                         SMEM_BYTES);
    dim3 grid(GX, BATCH);
    fused_kernel<<<grid, 256, SMEM_BYTES>>>(x, trafo, out);
}

// round 16
// speedup vs baseline: 1.0497x; 1.0497x over previous
#include <cuda_runtime.h>
#include <cuda_fp16.h>
#include <cstdint>

#define BATCH 512
#define GS 2048
#define PARAM 64
#define OGS 1024
#define KDIM 128
#define NDIM 64
#define TILE_ROWS 128
#define GX 8

#define PF  136                        // f32 pitch of A tile (544B: conflict-free LDS.64)
#define PFB (PF * 4)
#define SMEM_BYTES (TILE_ROWS * PFB)   // 69632

__device__ unsigned int g_order[BATCH * GS];
// B mma-fragments (single fp16): [ng(2)][kc(8)][g(2)][lane(32)] uint4. 16KB.
__device__ __align__(16) uint4 g_Bfrag[2 * 8 * 2 * 32];
__device__ int g_flag[BATCH];
__device__ int g_bflag;
__device__ unsigned int g_done;

__device__ __forceinline__ uint32_t smem_u32(const void* p) {
    uint32_t a;
    asm("{ .reg .u64 t; cvta.to.shared.u64 t, %1; cvt.u32.u64 %0, t; }" : "=r"(a) : "l"(p));
    return a;
}
__device__ __forceinline__ int ld_acquire(const int* p) {
    int v;
    asm volatile("ld.acquire.gpu.global.b32 %0, [%1];" : "=r"(v) : "l"(p) : "memory");
    return v;
}
__device__ __forceinline__ void st_release(int* p, int v) {
    asm volatile("st.release.gpu.global.b32 [%0], %1;" :: "l"(p), "r"(v) : "memory");
}

#define CPASYNC16(dst, src) \
    asm volatile("cp.async.cg.shared.global [%0], [%1], 16;" \
        :: "r"(dst), "l"(src) : "memory")

#define MMA(d, a, b0v, b1v) \
    asm volatile("mma.sync.aligned.m16n8k16.row.col.f32.f16.f16.f32 " \
        "{%0,%1,%2,%3},{%4,%5,%6,%7},{%8,%9},{%0,%1,%2,%3};" \
        : "+f"((d)[0]), "+f"((d)[1]), "+f"((d)[2]), "+f"((d)[3]) \
        : "r"((a)[0]), "r"((a)[1]), "r"((a)[2]), "r"((a)[3]), "r"(b0v), "r"(b1v))

// fp16 split: hi = f16x2(vx lo-half, vy hi-half); lo = f16x2 of residuals.
__device__ __forceinline__ void split_pair(float vx, float vy,
                                           uint32_t& hi, uint32_t& lo) {
    asm("cvt.rn.f16x2.f32 %0, %1, %2;" : "=r"(hi) : "f"(vy), "f"(vx));
    float hx, hy;
    asm("{ .reg .b16 l, h; mov.b32 {l, h}, %2; cvt.f32.f16 %0, l; cvt.f32.f16 %1, h; }"
        : "=f"(hx), "=f"(hy) : "r"(hi));
    float rx = vx - hx;
    float ry = vy - hy;
    asm("cvt.rn.f16x2.f32 %0, %1, %2;" : "=r"(lo) : "f"(ry), "f"(rx));
}

__device__ __forceinline__ void ce(unsigned long long& a, unsigned long long& b, bool up) {
    if ((a > b) == up) { unsigned long long t = a; a = b; b = t; }
}
__device__ __forceinline__ void merge8(unsigned long long* k, bool up) {
    ce(k[0], k[4], up); ce(k[1], k[5], up); ce(k[2], k[6], up); ce(k[3], k[7], up);
    ce(k[0], k[2], up); ce(k[1], k[3], up); ce(k[4], k[6], up); ce(k[5], k[7], up);
    ce(k[0], k[1], up); ce(k[2], k[3], up); ce(k[4], k[5], up); ce(k[6], k[7], up);
}

// ---------------------------------------------------------------------------
// Fused kernel. grid = (8, 512), block = 256, 2 CTAs/SM.
// After the sort, warps are fully independent: warp w gathers source rows
// 32w..32w+31 (-> A rows 16w..16w+15) via cp.async, then computes its
// M16xN64 output stripe. No intra-CTA barriers post-sort.
// ---------------------------------------------------------------------------
__global__ __launch_bounds__(256, 2) void fused_kernel(const float* __restrict__ x,
                                                       const float* __restrict__ trafo,
                                                       float* __restrict__ out) {
    extern __shared__ char smem[];
    __shared__ unsigned s_last;

    const int y = blockIdx.y;
    const int bid = blockIdx.x + y * GX;
    const int tileRow = blockIdx.x * TILE_ROWS;
    const int t = threadIdx.x;
    const int wid = t >> 5;
    const int lid = t & 31;
    const uint32_t sb32 = smem_u32(smem);

    // ---- B-fragment table (bid 0; 512 slots of 1 uint4, 2 per thread) ----
    if (bid == 0) {
        #pragma unroll
        for (int half = 0; half < 2; half++) {
            int it = t + 256 * half;
            int ng = it >> 8;
            int kc = (it >> 5) & 7;
            int lane = it & 31;
            int n_base = ng * 32 + (lane >> 2);
            int k_base = kc * 16 + 2 * (lane & 3);
            uint32_t rh[8];
            #pragma unroll
            for (int nt = 0; nt < 4; nt++)
                #pragma unroll
                for (int r = 0; r < 2; r++) {
                    int n = n_base + 8 * nt;
                    int k = k_base + 8 * r;
                    __half2 h2 = __floats2half2_rn(trafo[k * NDIM + n],
                                                   trafo[(k + 1) * NDIM + n]);
                    rh[2 * nt + r] = *(uint32_t*)&h2;
                }
            uint4* dst = g_Bfrag + (ng * 8 + kc) * 64 + lane;
            dst[0]  = make_uint4(rh[0], rh[1], rh[2], rh[3]);   // nt0, nt1 of this ng
            dst[32] = make_uint4(rh[4], rh[5], rh[6], rh[7]);   // nt2, nt3 of this ng
        }
        __syncthreads();
        __threadfence();
        if (t == 0) st_release(&g_bflag, 1);
    }

    // ---- Sort batch `bid` (bid < 512): 256 threads x 8 keys ----
    if (bid < BATCH) {
        unsigned long long* keys = (unsigned long long*)smem;   // 16KB overlay
        const float* xb = x + (size_t)bid * GS * PARAM;

        unsigned long long key[8];
        #pragma unroll
        for (int i = 0; i < 8; i++) {
            int e = 8 * t + i;
            unsigned u = __float_as_uint(xb[(size_t)e * PARAM + (PARAM - 1)]);
            unsigned m = (u & 0x80000000u) ? ~u : (u | 0x80000000u);
            key[i] = ((unsigned long long)(~m) << 32) | (unsigned)e;
        }

        ce(key[0], key[1], true);  ce(key[2], key[3], false);
        ce(key[4], key[5], true);  ce(key[6], key[7], false);
        ce(key[0], key[2], true);  ce(key[1], key[3], true);
        ce(key[0], key[1], true);  ce(key[2], key[3], true);
        ce(key[4], key[6], false); ce(key[5], key[7], false);
        ce(key[4], key[5], false); ce(key[6], key[7], false);
        merge8(key, (t & 1) == 0);

        #pragma unroll
        for (int k = 16; k <= 256; k <<= 1) {
            bool up = ((t & (k >> 3)) == 0);
            #pragma unroll
            for (int j = k >> 1; j >= 8; j >>= 1) {
                int d = j >> 3;
                bool keepmin = (((t & d) == 0) == up);
                #pragma unroll
                for (int i = 0; i < 8; i++) {
                    unsigned long long p = __shfl_xor_sync(0xffffffffu, key[i], d);
                    key[i] = keepmin ? (key[i] < p ? key[i] : p) : (key[i] > p ? key[i] : p);
                }
            }
            merge8(key, up);
        }

        for (int k = 512; k <= GS; k <<= 1) {
            #pragma unroll
            for (int i = 0; i < 8; i++) keys[8 * t + i] = key[i];
            __syncthreads();
            for (int j = k >> 1; j >= 256; j >>= 1) {
                #pragma unroll
                for (int q0 = 0; q0 < 4; q0++) {
                    int q = t + 256 * q0;
                    int i = ((q & ~(j - 1)) << 1) | (q & (j - 1));
                    bool up2 = ((i & k) == 0);
                    unsigned long long a = keys[i];
                    unsigned long long c = keys[i | j];
                    if ((a > c) == up2) { keys[i] = c; keys[i | j] = a; }
                }
                __syncthreads();
            }
            #pragma unroll
            for (int i = 0; i < 8; i++) key[i] = keys[8 * t + i];
            bool up = ((t & (k >> 3)) == 0);
            #pragma unroll
            for (int j = 128; j >= 8; j >>= 1) {
                int d = j >> 3;
                bool keepmin = (((t & d) == 0) == up);
                #pragma unroll
                for (int i = 0; i < 8; i++) {
                    unsigned long long p = __shfl_xor_sync(0xffffffffu, key[i], d);
                    key[i] = keepmin ? (key[i] < p ? key[i] : p) : (key[i] > p ? key[i] : p);
                }
            }
            merge8(key, up);
        }

        #pragma unroll
        for (int i = 0; i < 8; i++)
            g_order[bid * GS + 8 * t + i] = (unsigned)(key[i] & 0xffffffffu);

        __syncthreads();   // key reads done; smem reusable by gather
        __threadfence();
        if (t == 0) st_release(&g_flag[bid], 1);
    }

    // ---- Per-warp wait for this batch's order (sorter bid = y <= our bid) ----
    while (ld_acquire(&g_flag[y]) == 0) __nanosleep(64);

    // ---- Per-warp gather via cp.async: warp w fills A rows 16w..16w+15
    //      (source rows 32w..32w+31). 16 copies per thread, MLP 16.      ----
    {
        const int sbase = 32 * wid;
        const float* xb = x + (size_t)y * GS * PARAM;
        const int lane16 = lid & 15;
        const int rsel = lid >> 4;
        const unsigned* ord = g_order + y * GS + 2 * tileRow + sbase;
        unsigned idx[16];
        #pragma unroll
        for (int pass = 0; pass < 16; pass++)
            idx[pass] = ord[2 * pass + rsel];
        #pragma unroll
        for (int pass = 0; pass < 16; pass++) {
            int s = sbase + 2 * pass + rsel;
            const float* src = xb + (size_t)idx[pass] * PARAM + lane16 * 4;
            uint32_t dst = sb32 + (uint32_t)(s >> 1) * PFB +
                           (uint32_t)(((s & 1) * PARAM + lane16 * 4) * 4);
            CPASYNC16(dst, src);
        }
        asm volatile("cp.async.commit_group;" ::: "memory");
    }

    // ---- Overlap B-table wait with async-copy drain; warp-local sync ----
    while (ld_acquire(&g_bflag) == 0) __nanosleep(64);
    asm volatile("cp.async.wait_group 0;" ::: "memory");
    __syncwarp();

    // ---- Mainloop: warp w -> rows 16w..16w+15, ALL 64 cols. fp16 2-term.
    //      Each A element is split exactly once (no ng duplication).     ----
    const int wm = wid * 16;

    uint32_t a_base = sb32 + (uint32_t)(wm + (lid >> 2)) * PFB +
                      (uint32_t)(2 * (lid & 3) * 4);
    const uint32_t ROW8 = 8 * PFB;

    const uint4* Bf0 = g_Bfrag + lid;              // ng = 0 (cols 0..31)
    const uint4* Bf1 = g_Bfrag + 8 * 64 + lid;     // ng = 1 (cols 32..63)

    float d[8][4];
    #pragma unroll
    for (int nt = 0; nt < 8; nt++)
        #pragma unroll
        for (int e = 0; e < 4; e++) d[nt][e] = 0.f;

    #pragma unroll
    for (int kc = 0; kc < 8; kc++) {
        uint4 f0 = __ldg(Bf0 + kc * 64);          // nt0, nt1 (n 0..15)
        uint4 f1 = __ldg(Bf0 + kc * 64 + 32);     // nt2, nt3 (n 16..31)
        uint4 f2 = __ldg(Bf1 + kc * 64);          // nt4, nt5 (n 32..47)
        uint4 f3 = __ldg(Bf1 + kc * 64 + 32);     // nt6, nt7 (n 48..63)
        const uint32_t ab = a_base + kc * 64;

        float2 L0, L1, L2, L3;
        asm volatile("ld.shared.v2.f32 {%0,%1}, [%2];" : "=f"(L0.x), "=f"(L0.y) : "r"(ab));
        asm volatile("ld.shared.v2.f32 {%0,%1}, [%2];" : "=f"(L1.x), "=f"(L1.y) : "r"(ab + ROW8));
        asm volatile("ld.shared.v2.f32 {%0,%1}, [%2];" : "=f"(L2.x), "=f"(L2.y) : "r"(ab + 32));
        asm volatile("ld.shared.v2.f32 {%0,%1}, [%2];" : "=f"(L3.x), "=f"(L3.y) : "r"(ab + ROW8 + 32));

        uint32_t ah[4], al[4];
        split_pair(L0.x, L0.y, ah[0], al[0]);
        split_pair(L1.x, L1.y, ah[1], al[1]);
        split_pair(L2.x, L2.y, ah[2], al[2]);
        split_pair(L3.x, L3.y, ah[3], al[3]);

        MMA(d[0], ah, f0.x, f0.y);
        MMA(d[1], ah, f0.z, f0.w);
        MMA(d[2], ah, f1.x, f1.y);
        MMA(d[3], ah, f1.z, f1.w);
        MMA(d[4], ah, f2.x, f2.y);
        MMA(d[5], ah, f2.z, f2.w);
        MMA(d[6], ah, f3.x, f3.y);
        MMA(d[7], ah, f3.z, f3.w);
        MMA(d[0], al, f0.x, f0.y);
        MMA(d[1], al, f0.z, f0.w);
        MMA(d[2], al, f1.x, f1.y);
        MMA(d[3], al, f1.z, f1.w);
        MMA(d[4], al, f2.x, f2.y);
        MMA(d[5], al, f2.z, f2.w);
        MMA(d[6], al, f3.x, f3.y);
        MMA(d[7], al, f3.z, f3.w);
    }

    // ---- Epilogue: direct float2 stores (per-warp) ----
    float* baseo = out + ((size_t)y * OGS + tileRow) * NDIM;
    #pragma unroll
    for (int nt = 0; nt < 8; nt++) {
        int r = wm + (lid >> 2);
        int c = 8 * nt + 2 * (lid & 3);
        *(float2*)(baseo + (size_t)r * NDIM + c) = make_float2(d[nt][0], d[nt][1]);
        *(float2*)(baseo + (size_t)(r + 8) * NDIM + c) = make_float2(d[nt][2], d[nt][3]);
    }

    // ---- Flag reset by the last CTA to finish ----
    __syncthreads();
    if (t == 0) {
        unsigned done = atomicAdd(&g_done, 1u);
        s_last = (done == (unsigned)(GX * BATCH - 1)) ? 1u : 0u;
    }
    __syncthreads();
    if (s_last) {
        for (int i = t; i < BATCH; i += 256) g_flag[i] = 0;
        if (t == 0) { g_bflag = 0; g_done = 0u; }
    }
}

extern "C" void kernel_launch(void* const* d_in, const int* in_sizes, int n_in,
                              void* d_out, int out_size) {
    const float* x     = (const float*)d_in[0];
    const float* trafo = (const float*)d_in[1];
    float* out         = (float*)d_out;

    cudaFuncSetAttribute(fused_kernel, cudaFuncAttributeMaxDynamicSharedMemorySize,
                         SMEM_BYTES);
    dim3 grid(GX, BATCH);
    fused_kernel<<<grid, 256, SMEM_BYTES>>>(x, trafo, out);
}

// round 17
// speedup vs baseline: 1.0546x; 1.0047x over previous
#include <cuda_runtime.h>
#include <cuda_fp16.h>
#include <cstdint>

#define BATCH 512
#define GS 2048
#define PARAM 64
#define OGS 1024
#define KDIM 128
#define NDIM 64
#define TILE_ROWS 128
#define GX 8

#define PF  136                        // f32 pitch of A tile (544B: conflict-free LDS.64)
#define PFB (PF * 4)
#define SMEM_BYTES (TILE_ROWS * PFB)   // 69632

__device__ unsigned int g_order[BATCH * GS];
// B mma-fragments (single fp16): [ng(2)][kc(8)][g(2)][lane(32)] uint4. 16KB.
__device__ __align__(16) uint4 g_Bfrag[2 * 8 * 2 * 32];
__device__ int g_flag[BATCH];
__device__ int g_bflag;
__device__ unsigned int g_done;

__device__ __forceinline__ uint32_t smem_u32(const void* p) {
    uint32_t a;
    asm("{ .reg .u64 t; cvta.to.shared.u64 t, %1; cvt.u32.u64 %0, t; }" : "=r"(a) : "l"(p));
    return a;
}
__device__ __forceinline__ int ld_acquire(const int* p) {
    int v;
    asm volatile("ld.acquire.gpu.global.b32 %0, [%1];" : "=r"(v) : "l"(p) : "memory");
    return v;
}
__device__ __forceinline__ void st_release(int* p, int v) {
    asm volatile("st.release.gpu.global.b32 [%0], %1;" :: "l"(p), "r"(v) : "memory");
}

#define CPASYNC16(dst, src) \
    asm volatile("cp.async.cg.shared.global [%0], [%1], 16;" \
        :: "r"(dst), "l"(src) : "memory")

#define MMA(d, a, b0v, b1v) \
    asm volatile("mma.sync.aligned.m16n8k16.row.col.f32.f16.f16.f32 " \
        "{%0,%1,%2,%3},{%4,%5,%6,%7},{%8,%9},{%0,%1,%2,%3};" \
        : "+f"((d)[0]), "+f"((d)[1]), "+f"((d)[2]), "+f"((d)[3]) \
        : "r"((a)[0]), "r"((a)[1]), "r"((a)[2]), "r"((a)[3]), "r"(b0v), "r"(b1v))

#define LDS64(v, addr) \
    asm volatile("ld.shared.v2.f32 {%0,%1}, [%2];" : "=f"((v).x), "=f"((v).y) : "r"(addr))

// fp16 split: hi = f16x2(vx lo-half, vy hi-half); lo = f16x2 of residuals.
__device__ __forceinline__ void split_pair(float vx, float vy,
                                           uint32_t& hi, uint32_t& lo) {
    asm("cvt.rn.f16x2.f32 %0, %1, %2;" : "=r"(hi) : "f"(vy), "f"(vx));
    float hx, hy;
    asm("{ .reg .b16 l, h; mov.b32 {l, h}, %2; cvt.f32.f16 %0, l; cvt.f32.f16 %1, h; }"
        : "=f"(hx), "=f"(hy) : "r"(hi));
    float rx = vx - hx;
    float ry = vy - hy;
    asm("cvt.rn.f16x2.f32 %0, %1, %2;" : "=r"(lo) : "f"(ry), "f"(rx));
}

__device__ __forceinline__ void ce(unsigned long long& a, unsigned long long& b, bool up) {
    if ((a > b) == up) { unsigned long long t = a; a = b; b = t; }
}
__device__ __forceinline__ void merge8(unsigned long long* k, bool up) {
    ce(k[0], k[4], up); ce(k[1], k[5], up); ce(k[2], k[6], up); ce(k[3], k[7], up);
    ce(k[0], k[2], up); ce(k[1], k[3], up); ce(k[4], k[6], up); ce(k[5], k[7], up);
    ce(k[0], k[1], up); ce(k[2], k[3], up); ce(k[4], k[5], up); ce(k[6], k[7], up);
}

// ---------------------------------------------------------------------------
// Fused kernel. grid = (8, 512), block = 256, 2 CTAs/SM.
// Warp w: A rows 16w..16w+15 (cp.async gather), M16xN64 stripe, fp16 2-term.
// Mainloop software-pipelined: LDS for kc+1 issued before kc's MMA block.
// ---------------------------------------------------------------------------
__global__ __launch_bounds__(256, 2) void fused_kernel(const float* __restrict__ x,
                                                       const float* __restrict__ trafo,
                                                       float* __restrict__ out) {
    extern __shared__ char smem[];
    __shared__ unsigned s_last;

    const int y = blockIdx.y;
    const int bid = blockIdx.x + y * GX;
    const int tileRow = blockIdx.x * TILE_ROWS;
    const int t = threadIdx.x;
    const int wid = t >> 5;
    const int lid = t & 31;
    const uint32_t sb32 = smem_u32(smem);

    // ---- B-fragment table (bid 0; 512 slots of 1 uint4, 2 per thread) ----
    if (bid == 0) {
        #pragma unroll
        for (int half = 0; half < 2; half++) {
            int it = t + 256 * half;
            int ng = it >> 8;
            int kc = (it >> 5) & 7;
            int lane = it & 31;
            int n_base = ng * 32 + (lane >> 2);
            int k_base = kc * 16 + 2 * (lane & 3);
            uint32_t rh[8];
            #pragma unroll
            for (int nt = 0; nt < 4; nt++)
                #pragma unroll
                for (int r = 0; r < 2; r++) {
                    int n = n_base + 8 * nt;
                    int k = k_base + 8 * r;
                    __half2 h2 = __floats2half2_rn(trafo[k * NDIM + n],
                                                   trafo[(k + 1) * NDIM + n]);
                    rh[2 * nt + r] = *(uint32_t*)&h2;
                }
            uint4* dst = g_Bfrag + (ng * 8 + kc) * 64 + lane;
            dst[0]  = make_uint4(rh[0], rh[1], rh[2], rh[3]);
            dst[32] = make_uint4(rh[4], rh[5], rh[6], rh[7]);
        }
        __syncthreads();
        __threadfence();
        if (t == 0) st_release(&g_bflag, 1);
    }

    // ---- Sort batch `bid` (bid < 512): 256 threads x 8 keys ----
    if (bid < BATCH) {
        unsigned long long* keys = (unsigned long long*)smem;   // 16KB overlay
        const float* xb = x + (size_t)bid * GS * PARAM;

        unsigned long long key[8];
        #pragma unroll
        for (int i = 0; i < 8; i++) {
            int e = 8 * t + i;
            unsigned u = __float_as_uint(xb[(size_t)e * PARAM + (PARAM - 1)]);
            unsigned m = (u & 0x80000000u) ? ~u : (u | 0x80000000u);
            key[i] = ((unsigned long long)(~m) << 32) | (unsigned)e;
        }

        ce(key[0], key[1], true);  ce(key[2], key[3], false);
        ce(key[4], key[5], true);  ce(key[6], key[7], false);
        ce(key[0], key[2], true);  ce(key[1], key[3], true);
        ce(key[0], key[1], true);  ce(key[2], key[3], true);
        ce(key[4], key[6], false); ce(key[5], key[7], false);
        ce(key[4], key[5], false); ce(key[6], key[7], false);
        merge8(key, (t & 1) == 0);

        #pragma unroll
        for (int k = 16; k <= 256; k <<= 1) {
            bool up = ((t & (k >> 3)) == 0);
            #pragma unroll
            for (int j = k >> 1; j >= 8; j >>= 1) {
                int d = j >> 3;
                bool keepmin = (((t & d) == 0) == up);
                #pragma unroll
                for (int i = 0; i < 8; i++) {
                    unsigned long long p = __shfl_xor_sync(0xffffffffu, key[i], d);
                    key[i] = keepmin ? (key[i] < p ? key[i] : p) : (key[i] > p ? key[i] : p);
                }
            }
            merge8(key, up);
        }

        for (int k = 512; k <= GS; k <<= 1) {
            #pragma unroll
            for (int i = 0; i < 8; i++) keys[8 * t + i] = key[i];
            __syncthreads();
            for (int j = k >> 1; j >= 256; j >>= 1) {
                #pragma unroll
                for (int q0 = 0; q0 < 4; q0++) {
                    int q = t + 256 * q0;
                    int i = ((q & ~(j - 1)) << 1) | (q & (j - 1));
                    bool up2 = ((i & k) == 0);
                    unsigned long long a = keys[i];
                    unsigned long long c = keys[i | j];
                    if ((a > c) == up2) { keys[i] = c; keys[i | j] = a; }
                }
                __syncthreads();
            }
            #pragma unroll
            for (int i = 0; i < 8; i++) key[i] = keys[8 * t + i];
            bool up = ((t & (k >> 3)) == 0);
            #pragma unroll
            for (int j = 128; j >= 8; j >>= 1) {
                int d = j >> 3;
                bool keepmin = (((t & d) == 0) == up);
                #pragma unroll
                for (int i = 0; i < 8; i++) {
                    unsigned long long p = __shfl_xor_sync(0xffffffffu, key[i], d);
                    key[i] = keepmin ? (key[i] < p ? key[i] : p) : (key[i] > p ? key[i] : p);
                }
            }
            merge8(key, up);
        }

        #pragma unroll
        for (int i = 0; i < 8; i++)
            g_order[bid * GS + 8 * t + i] = (unsigned)(key[i] & 0xffffffffu);

        __syncthreads();   // key reads done; smem reusable by gather
        __threadfence();
        if (t == 0) st_release(&g_flag[bid], 1);
    }

    // ---- Per-warp wait for this batch's order (sorter bid = y <= our bid) ----
    while (ld_acquire(&g_flag[y]) == 0) __nanosleep(64);

    // ---- Per-warp gather via cp.async: warp w fills A rows 16w..16w+15 ----
    {
        const int sbase = 32 * wid;
        const float* xb = x + (size_t)y * GS * PARAM;
        const int lane16 = lid & 15;
        const int rsel = lid >> 4;
        const unsigned* ord = g_order + y * GS + 2 * tileRow + sbase;
        unsigned idx[16];
        #pragma unroll
        for (int pass = 0; pass < 16; pass++)
            idx[pass] = ord[2 * pass + rsel];
        #pragma unroll
        for (int pass = 0; pass < 16; pass++) {
            int s = sbase + 2 * pass + rsel;
            const float* src = xb + (size_t)idx[pass] * PARAM + lane16 * 4;
            uint32_t dst = sb32 + (uint32_t)(s >> 1) * PFB +
                           (uint32_t)(((s & 1) * PARAM + lane16 * 4) * 4);
            CPASYNC16(dst, src);
        }
        asm volatile("cp.async.commit_group;" ::: "memory");
    }

    // ---- Overlap B-table wait with async-copy drain; warp-local sync ----
    while (ld_acquire(&g_bflag) == 0) __nanosleep(64);
    asm volatile("cp.async.wait_group 0;" ::: "memory");
    __syncwarp();

    // ---- Mainloop (software-pipelined): warp w -> rows 16w..15, all 64 cols ----
    const int wm = wid * 16;

    uint32_t a_base = sb32 + (uint32_t)(wm + (lid >> 2)) * PFB +
                      (uint32_t)(2 * (lid & 3) * 4);
    const uint32_t ROW8 = 8 * PFB;

    const uint4* Bf0 = g_Bfrag + lid;              // ng = 0 (cols 0..31)
    const uint4* Bf1 = g_Bfrag + 8 * 64 + lid;     // ng = 1 (cols 32..63)

    float d[8][4];
    #pragma unroll
    for (int nt = 0; nt < 8; nt++)
        #pragma unroll
        for (int e = 0; e < 4; e++) d[nt][e] = 0.f;

    // Prologue: A-loads for kc = 0.
    float2 L0, L1, L2, L3;
    LDS64(L0, a_base);
    LDS64(L1, a_base + ROW8);
    LDS64(L2, a_base + 32);
    LDS64(L3, a_base + ROW8 + 32);

    #pragma unroll
    for (int kc = 0; kc < 8; kc++) {
        // B fragments for this kc (L1-hit LDGs, latency covered by split+MMA).
        uint4 f0 = __ldg(Bf0 + kc * 64);
        uint4 f1 = __ldg(Bf0 + kc * 64 + 32);
        uint4 f2 = __ldg(Bf1 + kc * 64);
        uint4 f3 = __ldg(Bf1 + kc * 64 + 32);

        // Prefetch next kc's A f32 pairs (LDS latency hidden by MMA block).
        float2 N0, N1, N2, N3;
        if (kc < 7) {
            const uint32_t an = a_base + (kc + 1) * 64;
            LDS64(N0, an);
            LDS64(N1, an + ROW8);
            LDS64(N2, an + 32);
            LDS64(N3, an + ROW8 + 32);
        }

        // Split current kc (values loaded a full iteration ago).
        uint32_t ah[4], al[4];
        split_pair(L0.x, L0.y, ah[0], al[0]);
        split_pair(L1.x, L1.y, ah[1], al[1]);
        split_pair(L2.x, L2.y, ah[2], al[2]);
        split_pair(L3.x, L3.y, ah[3], al[3]);

        MMA(d[0], ah, f0.x, f0.y);
        MMA(d[1], ah, f0.z, f0.w);
        MMA(d[2], ah, f1.x, f1.y);
        MMA(d[3], ah, f1.z, f1.w);
        MMA(d[4], ah, f2.x, f2.y);
        MMA(d[5], ah, f2.z, f2.w);
        MMA(d[6], ah, f3.x, f3.y);
        MMA(d[7], ah, f3.z, f3.w);
        MMA(d[0], al, f0.x, f0.y);
        MMA(d[1], al, f0.z, f0.w);
        MMA(d[2], al, f1.x, f1.y);
        MMA(d[3], al, f1.z, f1.w);
        MMA(d[4], al, f2.x, f2.y);
        MMA(d[5], al, f2.z, f2.w);
        MMA(d[6], al, f3.x, f3.y);
        MMA(d[7], al, f3.z, f3.w);

        if (kc < 7) { L0 = N0; L1 = N1; L2 = N2; L3 = N3; }
    }

    // ---- Epilogue: direct float2 stores (per-warp) ----
    float* baseo = out + ((size_t)y * OGS + tileRow) * NDIM;
    #pragma unroll
    for (int nt = 0; nt < 8; nt++) {
        int r = wm + (lid >> 2);
        int c = 8 * nt + 2 * (lid & 3);
        *(float2*)(baseo + (size_t)r * NDIM + c) = make_float2(d[nt][0], d[nt][1]);
        *(float2*)(baseo + (size_t)(r + 8) * NDIM + c) = make_float2(d[nt][2], d[nt][3]);
    }

    // ---- Flag reset by the last CTA to finish ----
    __syncthreads();
    if (t == 0) {
        unsigned done = atomicAdd(&g_done, 1u);
        s_last = (done == (unsigned)(GX * BATCH - 1)) ? 1u : 0u;
    }
    __syncthreads();
    if (s_last) {
        for (int i = t; i < BATCH; i += 256) g_flag[i] = 0;
        if (t == 0) { g_bflag = 0; g_done = 0u; }
    }
}

extern "C" void kernel_launch(void* const* d_in, const int* in_sizes, int n_in,
                              void* d_out, int out_size) {
    const float* x     = (const float*)d_in[0];
    const float* trafo = (const float*)d_in[1];
    float* out         = (float*)d_out;

    cudaFuncSetAttribute(fused_kernel, cudaFuncAttributeMaxDynamicSharedMemorySize,
                         SMEM_BYTES);
    dim3 grid(GX, BATCH);
    fused_kernel<<<grid, 256, SMEM_BYTES>>>(x, trafo, out);
}